// round 16
// baseline (speedup 1.0000x reference)
#include <cuda_runtime.h>

// Problem constants
#define BB 4
#define NN 2048
#define HH 8
#define DD 32
#define CC 256
#define QK_SCALE 0.17677669529663687f  // 32^-0.5

// Scratch (device globals; no allocations allowed)
__device__ float g_q[BB * HH * NN * DD];   // 8MB, [bh][n][d], pre-scaled by QK_SCALE
__device__ float g_k[BB * HH * NN * DD];   // 8MB
__device__ float g_v[BB * HH * NN * DD];   // 8MB
__device__ float g_bias[NN * NN];          // 16MB precomputed bias matrix
__device__ float g_ao[BB * NN * CC];       // 8MB attention output, [b][n][h*32+d]

// ---------------------------------------------------------------------------
// Kernel 1: QKV GEMM  y = x @ w_qkv, scatter into g_q (scaled), g_k, g_v
// x: [8192, 256], w: [256, 768]. BM=BN=128, BK=16, 256 thr, 8x8 per thread.
// ---------------------------------------------------------------------------
__global__ __launch_bounds__(256) void qkv_gemm(const float* __restrict__ x,
                                                const float* __restrict__ w) {
    __shared__ float As[16 * 132];  // transposed A tile, padded stride
    __shared__ float Bs[16 * 128];

    const int t  = threadIdx.x;
    const int n0 = blockIdx.x * 128;   // col tile (0..640)
    const int r0 = blockIdx.y * 128;   // row tile
    const int tm = (t >> 4) << 3;
    const int tn = (t & 15) << 3;

    float acc[8][8] = {};

    for (int k0 = 0; k0 < 256; k0 += 16) {
#pragma unroll
        for (int u = 0; u < 2; u++) {
            int f = t + u * 256;            // 0..511 float4s of A tile
            int row = f >> 2, c4 = f & 3;
            float4 v = *(const float4*)(x + (size_t)(r0 + row) * 256 + k0 + c4 * 4);
            As[(c4 * 4 + 0) * 132 + row] = v.x;
            As[(c4 * 4 + 1) * 132 + row] = v.y;
            As[(c4 * 4 + 2) * 132 + row] = v.z;
            As[(c4 * 4 + 3) * 132 + row] = v.w;
        }
#pragma unroll
        for (int u = 0; u < 2; u++) {
            int f = t + u * 256;
            int kr = f >> 5, c4 = f & 31;
            *(float4*)(Bs + kr * 128 + c4 * 4) =
                *(const float4*)(w + (size_t)(k0 + kr) * 768 + n0 + c4 * 4);
        }
        __syncthreads();
#pragma unroll
        for (int k = 0; k < 16; k++) {
            float a[8], b[8];
            *(float4*)(a)     = *(const float4*)(As + k * 132 + tm);
            *(float4*)(a + 4) = *(const float4*)(As + k * 132 + tm + 4);
            *(float4*)(b)     = *(const float4*)(Bs + k * 128 + tn);
            *(float4*)(b + 4) = *(const float4*)(Bs + k * 128 + tn + 4);
#pragma unroll
            for (int i = 0; i < 8; i++)
#pragma unroll
                for (int j = 0; j < 8; j++) acc[i][j] += a[i] * b[j];
        }
        __syncthreads();
    }

    // Scatter epilogue: col -> (three, h, d); row -> (b, n)
    const int colbase = n0 + tn;           // 8-aligned; stays within one 32-wide d block
    const int three = colbase >> 8;
    const int h = (colbase >> 5) & 7;
    const int d0 = colbase & 31;
    float* dst = (three == 0) ? g_q : ((three == 1) ? g_k : g_v);
    const float sc = (three == 0) ? QK_SCALE : 1.0f;

#pragma unroll
    for (int i = 0; i < 8; i++) {
        int row = r0 + tm + i;
        int b_ = row >> 11;
        int n  = row & 2047;
        float* p = dst + (((size_t)(b_ * HH + h)) * NN + n) * DD + d0;
        float4 v0 = make_float4(acc[i][0] * sc, acc[i][1] * sc, acc[i][2] * sc, acc[i][3] * sc);
        float4 v1 = make_float4(acc[i][4] * sc, acc[i][5] * sc, acc[i][6] * sc, acc[i][7] * sc);
        *(float4*)(p)     = v0;
        *(float4*)(p + 4) = v1;
    }
}

// ---------------------------------------------------------------------------
// Kernel 2: bias precompute  g_bias[i] = bias_table[relative_pos[i]]
// ---------------------------------------------------------------------------
__global__ __launch_bounds__(256) void bias_gather(const float* __restrict__ table,
                                                   const int* __restrict__ rp) {
    int i4 = blockIdx.x * blockDim.x + threadIdx.x;   // NN*NN/4 = 1M float4s
    int4 r = ((const int4*)rp)[i4];
    float4 o = make_float4(__ldg(table + r.x), __ldg(table + r.y),
                           __ldg(table + r.z), __ldg(table + r.w));
    ((float4*)g_bias)[i4] = o;
}

// ---------------------------------------------------------------------------
// Kernel 3: attention (no-max softmax, fused).
// Grid: (16 q-tiles, 32 bh). 256 threads. TQ=128, TK=128.
// Phase A: S = exp(Q Kt + bias) -> Ps (transposed [m][q])
// Phase B: O += Ps^T V; denom accumulated by warp 0. Final: O/denom.
// ---------------------------------------------------------------------------
__global__ __launch_bounds__(256, 2) void attn_kernel() {
    extern __shared__ float sm[];
    float* QsT = sm;            // [32][128]  (Qs[d][q])
    float* KsT = sm + 4096;     // [32][128]  (Ks[d][m])
    float* Vs  = sm + 8192;     // [128][32]
    float* Ps  = sm + 12288;    // [128][128] (Ps[m][q])

    const int t   = threadIdx.x;
    const int bh  = blockIdx.y;           // 0..31
    const int q0g = blockIdx.x * 128;     // global q base

    const float* __restrict__ Qg = g_q + (size_t)bh * NN * DD + (size_t)q0g * DD;
    const float* __restrict__ Kg = g_k + (size_t)bh * NN * DD;
    const float* __restrict__ Vg = g_v + (size_t)bh * NN * DD;

    // Load Q tile transposed (once). Tile is one contiguous 16KB chunk.
#pragma unroll
    for (int u = 0; u < 4; u++) {
        int f = t + u * 256;              // 0..1023 float4s
        int row = f >> 3, c4 = f & 7;
        float4 v = *(const float4*)(Qg + row * 32 + c4 * 4);
        QsT[(c4 * 4 + 0) * 128 + row] = v.x;
        QsT[(c4 * 4 + 1) * 128 + row] = v.y;
        QsT[(c4 * 4 + 2) * 128 + row] = v.z;
        QsT[(c4 * 4 + 3) * 128 + row] = v.w;
    }

    // Phase A thread mapping: 16 q-groups x 16 m-groups of 8x8
    const int qg = (t & 15) << 3;
    const int mg = (t >> 4) << 3;
    // Phase B thread mapping: 32 q-groups(4) x 8 d-groups(4)
    const int qb = (t & 31) << 2;
    const int db = (t >> 5) << 2;

    float oacc[4][4] = {};
    float dacc[4] = {0.f, 0.f, 0.f, 0.f};

    for (int kt = 0; kt < 16; kt++) {
        const int m0 = kt * 128;
        __syncthreads();  // previous phase B done reading Vs/Ps

        // Load K tile (transposed) + V tile (natural)
#pragma unroll
        for (int u = 0; u < 4; u++) {
            int f = t + u * 256;
            int row = f >> 3, c4 = f & 7;
            float4 kv = *(const float4*)(Kg + (size_t)(m0 + row) * 32 + c4 * 4);
            KsT[(c4 * 4 + 0) * 128 + row] = kv.x;
            KsT[(c4 * 4 + 1) * 128 + row] = kv.y;
            KsT[(c4 * 4 + 2) * 128 + row] = kv.z;
            KsT[(c4 * 4 + 3) * 128 + row] = kv.w;
            float4 vv = *(const float4*)(Vg + (size_t)(m0 + row) * 32 + c4 * 4);
            *(float4*)(Vs + row * 32 + c4 * 4) = vv;
        }
        __syncthreads();

        // Phase A: 8x8 S micro-tile, dot over D=32
        float acc[8][8] = {};
#pragma unroll 8
        for (int k = 0; k < 32; k++) {
            float a[8], b[8];
            *(float4*)(a)     = *(const float4*)(QsT + k * 128 + qg);
            *(float4*)(a + 4) = *(const float4*)(QsT + k * 128 + qg + 4);
            *(float4*)(b)     = *(const float4*)(KsT + k * 128 + mg);
            *(float4*)(b + 4) = *(const float4*)(KsT + k * 128 + mg + 4);
#pragma unroll
            for (int i = 0; i < 8; i++)
#pragma unroll
                for (int j = 0; j < 8; j++) acc[i][j] += a[i] * b[j];
        }
        // bias + exp, store P transposed
#pragma unroll
        for (int i = 0; i < 8; i++) {
            const float* bp = g_bias + (size_t)(q0g + qg + i) * NN + m0 + mg;
            float4 b0 = *(const float4*)(bp);
            float4 b1 = *(const float4*)(bp + 4);
            float pb[8];
            pb[0] = __expf(acc[i][0] + b0.x);
            pb[1] = __expf(acc[i][1] + b0.y);
            pb[2] = __expf(acc[i][2] + b0.z);
            pb[3] = __expf(acc[i][3] + b0.w);
            pb[4] = __expf(acc[i][4] + b1.x);
            pb[5] = __expf(acc[i][5] + b1.y);
            pb[6] = __expf(acc[i][6] + b1.z);
            pb[7] = __expf(acc[i][7] + b1.w);
#pragma unroll
            for (int j = 0; j < 8; j++) Ps[(mg + j) * 128 + qg + i] = pb[j];
        }
        __syncthreads();

        // Phase B: O[q][d] += sum_m P[m][q] * V[m][d]; warp 0 also sums denom
#pragma unroll 4
        for (int m = 0; m < 128; m++) {
            float4 pv = *(const float4*)(Ps + m * 128 + qb);
            float4 vv = *(const float4*)(Vs + m * 32 + db);
            float p[4] = {pv.x, pv.y, pv.z, pv.w};
            float v[4] = {vv.x, vv.y, vv.z, vv.w};
#pragma unroll
            for (int i = 0; i < 4; i++)
#pragma unroll
                for (int j = 0; j < 4; j++) oacc[i][j] += p[i] * v[j];
            if (db == 0) {  // warp-uniform: only warp 0
#pragma unroll
                for (int i = 0; i < 4; i++) dacc[i] += p[i];
            }
        }
    }

    // Share denominators (reuse QsT region; disjoint from Ps/Vs, so safe)
    float* dsum = sm;
    if (db == 0) {
#pragma unroll
        for (int i = 0; i < 4; i++) dsum[qb + i] = dacc[i];
    }
    __syncthreads();

    const int b_ = bh >> 3, h = bh & 7;
#pragma unroll
    for (int i = 0; i < 4; i++) {
        float inv = 1.0f / dsum[qb + i];
        float4 o = make_float4(oacc[i][0] * inv, oacc[i][1] * inv,
                               oacc[i][2] * inv, oacc[i][3] * inv);
        *(float4*)(g_ao + ((size_t)(b_ * NN + q0g + qb + i)) * CC + h * DD + db) = o;
    }
}

// ---------------------------------------------------------------------------
// Kernel 4: output projection  out = g_ao @ w_out + b_out
// [8192,256] @ [256,256]. Same tiling as kernel 1.
// ---------------------------------------------------------------------------
__global__ __launch_bounds__(256) void out_gemm(const float* __restrict__ w,
                                                const float* __restrict__ bias,
                                                float* __restrict__ out) {
    __shared__ float As[16 * 132];
    __shared__ float Bs[16 * 128];

    const int t  = threadIdx.x;
    const int n0 = blockIdx.x * 128;   // 0 or 128
    const int r0 = blockIdx.y * 128;
    const int tm = (t >> 4) << 3;
    const int tn = (t & 15) << 3;

    float acc[8][8] = {};

    for (int k0 = 0; k0 < 256; k0 += 16) {
#pragma unroll
        for (int u = 0; u < 2; u++) {
            int f = t + u * 256;
            int row = f >> 2, c4 = f & 3;
            float4 v = *(const float4*)(g_ao + (size_t)(r0 + row) * 256 + k0 + c4 * 4);
            As[(c4 * 4 + 0) * 132 + row] = v.x;
            As[(c4 * 4 + 1) * 132 + row] = v.y;
            As[(c4 * 4 + 2) * 132 + row] = v.z;
            As[(c4 * 4 + 3) * 132 + row] = v.w;
        }
#pragma unroll
        for (int u = 0; u < 2; u++) {
            int f = t + u * 256;
            int kr = f >> 5, c4 = f & 31;
            *(float4*)(Bs + kr * 128 + c4 * 4) =
                *(const float4*)(w + (size_t)(k0 + kr) * 256 + n0 + c4 * 4);
        }
        __syncthreads();
#pragma unroll
        for (int k = 0; k < 16; k++) {
            float a[8], b[8];
            *(float4*)(a)     = *(const float4*)(As + k * 132 + tm);
            *(float4*)(a + 4) = *(const float4*)(As + k * 132 + tm + 4);
            *(float4*)(b)     = *(const float4*)(Bs + k * 128 + tn);
            *(float4*)(b + 4) = *(const float4*)(Bs + k * 128 + tn + 4);
#pragma unroll
            for (int i = 0; i < 8; i++)
#pragma unroll
                for (int j = 0; j < 8; j++) acc[i][j] += a[i] * b[j];
        }
        __syncthreads();
    }

    float bj[8];
    *(float4*)(bj)     = *(const float4*)(bias + n0 + tn);
    *(float4*)(bj + 4) = *(const float4*)(bias + n0 + tn + 4);

#pragma unroll
    for (int i = 0; i < 8; i++) {
        int row = r0 + tm + i;
        float* p = out + (size_t)row * 256 + n0 + tn;
        float4 v0 = make_float4(acc[i][0] + bj[0], acc[i][1] + bj[1],
                                acc[i][2] + bj[2], acc[i][3] + bj[3]);
        float4 v1 = make_float4(acc[i][4] + bj[4], acc[i][5] + bj[5],
                                acc[i][6] + bj[6], acc[i][7] + bj[7]);
        *(float4*)(p)     = v0;
        *(float4*)(p + 4) = v1;
    }
}

// ---------------------------------------------------------------------------
extern "C" void kernel_launch(void* const* d_in, const int* in_sizes, int n_in,
                              void* d_out, int out_size) {
    (void)in_sizes; (void)n_in; (void)out_size;
    const float* x      = (const float*)d_in[0];  // [4,2048,256]
    const float* w_qkv  = (const float*)d_in[1];  // [256,768]
    const float* table  = (const float*)d_in[2];  // [16384,1]
    const float* w_out  = (const float*)d_in[3];  // [256,256]
    const float* b_out  = (const float*)d_in[4];  // [256]
    const int*   rp     = (const int*)d_in[5];    // [2048,2048]
    float* out = (float*)d_out;

    cudaFuncSetAttribute(attn_kernel, cudaFuncAttributeMaxDynamicSharedMemorySize,
                         114688);  // 112KB dynamic smem

    qkv_gemm<<<dim3(6, 64), 256>>>(x, w_qkv);
    bias_gather<<<dim3((NN * NN / 4) / 256), 256>>>(table, rp);
    attn_kernel<<<dim3(16, 32), 256, 114688>>>();
    out_gemm<<<dim3(2, 64), 256>>>(w_out, b_out, out);
}

// round 17
// speedup vs baseline: 1.0022x; 1.0022x over previous
#include <cuda_runtime.h>

// Problem constants
#define BB 4
#define NN 2048
#define HH 8
#define DD 32
#define CC 256
#define QK_SCALE 0.17677669529663687f  // 32^-0.5

// Scratch (device globals; no allocations allowed)
__device__ float g_q[BB * HH * NN * DD];   // 8MB, [bh][n][d], pre-scaled by QK_SCALE
__device__ float g_k[BB * HH * NN * DD];   // 8MB
__device__ float g_v[BB * HH * NN * DD];   // 8MB
__device__ float g_bias[NN * NN];          // 16MB precomputed bias matrix
__device__ float g_ao[BB * NN * CC];       // 8MB attention output, [b][n][h*32+d]

// ---------------------------------------------------------------------------
// Kernel 1: QKV GEMM  y = x @ w_qkv, scatter into g_q (scaled), g_k, g_v
// x: [8192, 256], w: [256, 768]. BM=BN=128, BK=16, 256 thr, 8x8 per thread.
// ---------------------------------------------------------------------------
__global__ __launch_bounds__(256) void qkv_gemm(const float* __restrict__ x,
                                                const float* __restrict__ w) {
    __shared__ float As[16 * 132];  // transposed A tile, padded stride
    __shared__ float Bs[16 * 128];

    const int t  = threadIdx.x;
    const int n0 = blockIdx.x * 128;   // col tile (0..640)
    const int r0 = blockIdx.y * 128;   // row tile
    const int tm = (t >> 4) << 3;
    const int tn = (t & 15) << 3;

    float acc[8][8] = {};

    for (int k0 = 0; k0 < 256; k0 += 16) {
#pragma unroll
        for (int u = 0; u < 2; u++) {
            int f = t + u * 256;            // 0..511 float4s of A tile
            int row = f >> 2, c4 = f & 3;
            float4 v = *(const float4*)(x + (size_t)(r0 + row) * 256 + k0 + c4 * 4);
            As[(c4 * 4 + 0) * 132 + row] = v.x;
            As[(c4 * 4 + 1) * 132 + row] = v.y;
            As[(c4 * 4 + 2) * 132 + row] = v.z;
            As[(c4 * 4 + 3) * 132 + row] = v.w;
        }
#pragma unroll
        for (int u = 0; u < 2; u++) {
            int f = t + u * 256;
            int kr = f >> 5, c4 = f & 31;
            *(float4*)(Bs + kr * 128 + c4 * 4) =
                *(const float4*)(w + (size_t)(k0 + kr) * 768 + n0 + c4 * 4);
        }
        __syncthreads();
#pragma unroll
        for (int k = 0; k < 16; k++) {
            float a[8], b[8];
            *(float4*)(a)     = *(const float4*)(As + k * 132 + tm);
            *(float4*)(a + 4) = *(const float4*)(As + k * 132 + tm + 4);
            *(float4*)(b)     = *(const float4*)(Bs + k * 128 + tn);
            *(float4*)(b + 4) = *(const float4*)(Bs + k * 128 + tn + 4);
#pragma unroll
            for (int i = 0; i < 8; i++)
#pragma unroll
                for (int j = 0; j < 8; j++) acc[i][j] += a[i] * b[j];
        }
        __syncthreads();
    }

    // Scatter epilogue: col -> (three, h, d); row -> (b, n)
    const int colbase = n0 + tn;           // 8-aligned; stays within one 32-wide d block
    const int three = colbase >> 8;
    const int h = (colbase >> 5) & 7;
    const int d0 = colbase & 31;
    float* dst = (three == 0) ? g_q : ((three == 1) ? g_k : g_v);
    const float sc = (three == 0) ? QK_SCALE : 1.0f;

#pragma unroll
    for (int i = 0; i < 8; i++) {
        int row = r0 + tm + i;
        int b_ = row >> 11;
        int n  = row & 2047;
        float* p = dst + (((size_t)(b_ * HH + h)) * NN + n) * DD + d0;
        float4 v0 = make_float4(acc[i][0] * sc, acc[i][1] * sc, acc[i][2] * sc, acc[i][3] * sc);
        float4 v1 = make_float4(acc[i][4] * sc, acc[i][5] * sc, acc[i][6] * sc, acc[i][7] * sc);
        *(float4*)(p)     = v0;
        *(float4*)(p + 4) = v1;
    }
}

// ---------------------------------------------------------------------------
// Kernel 2: bias precompute  g_bias[i] = bias_table[relative_pos[i]]
// ---------------------------------------------------------------------------
__global__ __launch_bounds__(256) void bias_gather(const float* __restrict__ table,
                                                   const int* __restrict__ rp) {
    int i4 = blockIdx.x * blockDim.x + threadIdx.x;   // NN*NN/4 = 1M float4s
    int4 r = ((const int4*)rp)[i4];
    float4 o = make_float4(__ldg(table + r.x), __ldg(table + r.y),
                           __ldg(table + r.z), __ldg(table + r.w));
    ((float4*)g_bias)[i4] = o;
}

// ---------------------------------------------------------------------------
// Kernel 3: attention (no-max softmax, fused).
// Grid: (16 q-tiles, 32 bh). 256 threads. TQ=128, TK=128.
// Phase A: S = exp(Q Kt + bias) -> Ps (transposed [m][q])
// Phase B: O += Ps^T V; denom accumulated by warp 0. Final: O/denom.
// ---------------------------------------------------------------------------
__global__ __launch_bounds__(256, 2) void attn_kernel() {
    extern __shared__ float sm[];
    float* QsT = sm;            // [32][128]  (Qs[d][q])
    float* KsT = sm + 4096;     // [32][128]  (Ks[d][m])
    float* Vs  = sm + 8192;     // [128][32]
    float* Ps  = sm + 12288;    // [128][128] (Ps[m][q])

    const int t   = threadIdx.x;
    const int bh  = blockIdx.y;           // 0..31
    const int q0g = blockIdx.x * 128;     // global q base

    const float* __restrict__ Qg = g_q + (size_t)bh * NN * DD + (size_t)q0g * DD;
    const float* __restrict__ Kg = g_k + (size_t)bh * NN * DD;
    const float* __restrict__ Vg = g_v + (size_t)bh * NN * DD;

    // Load Q tile transposed (once). Tile is one contiguous 16KB chunk.
#pragma unroll
    for (int u = 0; u < 4; u++) {
        int f = t + u * 256;              // 0..1023 float4s
        int row = f >> 3, c4 = f & 7;
        float4 v = *(const float4*)(Qg + row * 32 + c4 * 4);
        QsT[(c4 * 4 + 0) * 128 + row] = v.x;
        QsT[(c4 * 4 + 1) * 128 + row] = v.y;
        QsT[(c4 * 4 + 2) * 128 + row] = v.z;
        QsT[(c4 * 4 + 3) * 128 + row] = v.w;
    }

    // Phase A thread mapping: 16 q-groups x 16 m-groups of 8x8
    const int qg = (t & 15) << 3;
    const int mg = (t >> 4) << 3;
    // Phase B thread mapping: 32 q-groups(4) x 8 d-groups(4)
    const int qb = (t & 31) << 2;
    const int db = (t >> 5) << 2;

    float oacc[4][4] = {};
    float dacc[4] = {0.f, 0.f, 0.f, 0.f};

    for (int kt = 0; kt < 16; kt++) {
        const int m0 = kt * 128;
        __syncthreads();  // previous phase B done reading Vs/Ps

        // Load K tile (transposed) + V tile (natural)
#pragma unroll
        for (int u = 0; u < 4; u++) {
            int f = t + u * 256;
            int row = f >> 3, c4 = f & 7;
            float4 kv = *(const float4*)(Kg + (size_t)(m0 + row) * 32 + c4 * 4);
            KsT[(c4 * 4 + 0) * 128 + row] = kv.x;
            KsT[(c4 * 4 + 1) * 128 + row] = kv.y;
            KsT[(c4 * 4 + 2) * 128 + row] = kv.z;
            KsT[(c4 * 4 + 3) * 128 + row] = kv.w;
            float4 vv = *(const float4*)(Vg + (size_t)(m0 + row) * 32 + c4 * 4);
            *(float4*)(Vs + row * 32 + c4 * 4) = vv;
        }
        __syncthreads();

        // Phase A: 8x8 S micro-tile, dot over D=32
        float acc[8][8] = {};
#pragma unroll 8
        for (int k = 0; k < 32; k++) {
            float a[8], b[8];
            *(float4*)(a)     = *(const float4*)(QsT + k * 128 + qg);
            *(float4*)(a + 4) = *(const float4*)(QsT + k * 128 + qg + 4);
            *(float4*)(b)     = *(const float4*)(KsT + k * 128 + mg);
            *(float4*)(b + 4) = *(const float4*)(KsT + k * 128 + mg + 4);
#pragma unroll
            for (int i = 0; i < 8; i++)
#pragma unroll
                for (int j = 0; j < 8; j++) acc[i][j] += a[i] * b[j];
        }
        // bias + exp, store P transposed
#pragma unroll
        for (int i = 0; i < 8; i++) {
            const float* bp = g_bias + (size_t)(q0g + qg + i) * NN + m0 + mg;
            float4 b0 = *(const float4*)(bp);
            float4 b1 = *(const float4*)(bp + 4);
            float pb[8];
            pb[0] = __expf(acc[i][0] + b0.x);
            pb[1] = __expf(acc[i][1] + b0.y);
            pb[2] = __expf(acc[i][2] + b0.z);
            pb[3] = __expf(acc[i][3] + b0.w);
            pb[4] = __expf(acc[i][4] + b1.x);
            pb[5] = __expf(acc[i][5] + b1.y);
            pb[6] = __expf(acc[i][6] + b1.z);
            pb[7] = __expf(acc[i][7] + b1.w);
#pragma unroll
            for (int j = 0; j < 8; j++) Ps[(mg + j) * 128 + qg + i] = pb[j];
        }
        __syncthreads();

        // Phase B: O[q][d] += sum_m P[m][q] * V[m][d]; warp 0 also sums denom
#pragma unroll 4
        for (int m = 0; m < 128; m++) {
            float4 pv = *(const float4*)(Ps + m * 128 + qb);
            float4 vv = *(const float4*)(Vs + m * 32 + db);
            float p[4] = {pv.x, pv.y, pv.z, pv.w};
            float v[4] = {vv.x, vv.y, vv.z, vv.w};
#pragma unroll
            for (int i = 0; i < 4; i++)
#pragma unroll
                for (int j = 0; j < 4; j++) oacc[i][j] += p[i] * v[j];
            if (db == 0) {  // warp-uniform: only warp 0
#pragma unroll
                for (int i = 0; i < 4; i++) dacc[i] += p[i];
            }
        }
    }

    // Share denominators (reuse QsT region; disjoint from Ps/Vs, so safe)
    float* dsum = sm;
    if (db == 0) {
#pragma unroll
        for (int i = 0; i < 4; i++) dsum[qb + i] = dacc[i];
    }
    __syncthreads();

    const int b_ = bh >> 3, h = bh & 7;
#pragma unroll
    for (int i = 0; i < 4; i++) {
        float inv = 1.0f / dsum[qb + i];
        float4 o = make_float4(oacc[i][0] * inv, oacc[i][1] * inv,
                               oacc[i][2] * inv, oacc[i][3] * inv);
        *(float4*)(g_ao + ((size_t)(b_ * NN + q0g + qb + i)) * CC + h * DD + db) = o;
    }
}

// ---------------------------------------------------------------------------
// Kernel 4: output projection  out = g_ao @ w_out + b_out
// [8192,256] @ [256,256]. Same tiling as kernel 1.
// ---------------------------------------------------------------------------
__global__ __launch_bounds__(256) void out_gemm(const float* __restrict__ w,
                                                const float* __restrict__ bias,
                                                float* __restrict__ out) {
    __shared__ float As[16 * 132];
    __shared__ float Bs[16 * 128];

    const int t  = threadIdx.x;
    const int n0 = blockIdx.x * 128;   // 0 or 128
    const int r0 = blockIdx.y * 128;
    const int tm = (t >> 4) << 3;
    const int tn = (t & 15) << 3;

    float acc[8][8] = {};

    for (int k0 = 0; k0 < 256; k0 += 16) {
#pragma unroll
        for (int u = 0; u < 2; u++) {
            int f = t + u * 256;
            int row = f >> 2, c4 = f & 3;
            float4 v = *(const float4*)(g_ao + (size_t)(r0 + row) * 256 + k0 + c4 * 4);
            As[(c4 * 4 + 0) * 132 + row] = v.x;
            As[(c4 * 4 + 1) * 132 + row] = v.y;
            As[(c4 * 4 + 2) * 132 + row] = v.z;
            As[(c4 * 4 + 3) * 132 + row] = v.w;
        }
#pragma unroll
        for (int u = 0; u < 2; u++) {
            int f = t + u * 256;
            int kr = f >> 5, c4 = f & 31;
            *(float4*)(Bs + kr * 128 + c4 * 4) =
                *(const float4*)(w + (size_t)(k0 + kr) * 256 + n0 + c4 * 4);
        }
        __syncthreads();
#pragma unroll
        for (int k = 0; k < 16; k++) {
            float a[8], b[8];
            *(float4*)(a)     = *(const float4*)(As + k * 132 + tm);
            *(float4*)(a + 4) = *(const float4*)(As + k * 132 + tm + 4);
            *(float4*)(b)     = *(const float4*)(Bs + k * 128 + tn);
            *(float4*)(b + 4) = *(const float4*)(Bs + k * 128 + tn + 4);
#pragma unroll
            for (int i = 0; i < 8; i++)
#pragma unroll
                for (int j = 0; j < 8; j++) acc[i][j] += a[i] * b[j];
        }
        __syncthreads();
    }

    float bj[8];
    *(float4*)(bj)     = *(const float4*)(bias + n0 + tn);
    *(float4*)(bj + 4) = *(const float4*)(bias + n0 + tn + 4);

#pragma unroll
    for (int i = 0; i < 8; i++) {
        int row = r0 + tm + i;
        float* p = out + (size_t)row * 256 + n0 + tn;
        float4 v0 = make_float4(acc[i][0] + bj[0], acc[i][1] + bj[1],
                                acc[i][2] + bj[2], acc[i][3] + bj[3]);
        float4 v1 = make_float4(acc[i][4] + bj[4], acc[i][5] + bj[5],
                                acc[i][6] + bj[6], acc[i][7] + bj[7]);
        *(float4*)(p)     = v0;
        *(float4*)(p + 4) = v1;
    }
}

// ---------------------------------------------------------------------------
extern "C" void kernel_launch(void* const* d_in, const int* in_sizes, int n_in,
                              void* d_out, int out_size) {
    (void)in_sizes; (void)n_in; (void)out_size;
    const float* x      = (const float*)d_in[0];  // [4,2048,256]
    const float* w_qkv  = (const float*)d_in[1];  // [256,768]
    const float* table  = (const float*)d_in[2];  // [16384,1]
    const float* w_out  = (const float*)d_in[3];  // [256,256]
    const float* b_out  = (const float*)d_in[4];  // [256]
    const int*   rp     = (const int*)d_in[5];    // [2048,2048]
    float* out = (float*)d_out;

    cudaFuncSetAttribute(attn_kernel, cudaFuncAttributeMaxDynamicSharedMemorySize,
                         114688);  // 112KB dynamic smem

    qkv_gemm<<<dim3(6, 64), 256>>>(x, w_qkv);
    bias_gather<<<dim3((NN * NN / 4) / 256), 256>>>(table, rp);
    attn_kernel<<<dim3(16, 32), 256, 114688>>>();
    out_gemm<<<dim3(2, 64), 256>>>(w_out, b_out, out);
}